// round 7
// baseline (speedup 1.0000x reference)
#include <cuda_runtime.h>
#include <cuda_fp16.h>
#include <cstdint>
#include <cstddef>

#define Bn 256
#define Sn 128
#define En 1024

constexpr int MT   = 192;           // two 96-row bags stacked
constexpr int NT   = 128;           // f-columns per chunk
constexpr int KT   = 64;            // K halfs per tile (128B rows)
constexpr int NFC  = En / NT;       // 8
constexpr int NKT  = En / KT;       // 16
constexpr int TILES = NFC * NKT;    // 128
constexpr int NTHR = 384;           // 12 warps: 3 (M, interleaved mod 3) x 4 (N, 32 cols)
constexpr int WMN  = 3;
constexpr int WNN  = 4;
constexpr int STAGES = 4;
constexpr int NBLK = Bn / 2;        // 128 CTAs, 2 bags each

constexpr int A_TILE_B = MT * KT * 2;   // 24576
constexpr int B_TILE_B = NT * KT * 2;   // 16384
constexpr int STG_B    = A_TILE_B + B_TILE_B;          // 40960
constexpr int OFF_U    = STAGES * STG_B;               // 163840
constexpr int OFF_SP   = OFF_U + En * 4;               // 167936
constexpr int OFF_AT   = OFF_SP + MT * WNN * 4;        // 171008
constexpr int SMEM_TOTAL = OFF_AT + MT * 4;            // 171776

// device-global scratch (allocations are forbidden)
__device__ __half g_Wh[En * En];
__device__ __half g_xh[Bn * Sn * En];

// ---------------------------------------------------------------------------
__device__ __forceinline__ void cp16(uint32_t dst, const void* src, bool pred) {
    int sz = pred ? 16 : 0;
    asm volatile("cp.async.cg.shared.global [%0], [%1], 16, %2;\n"
                 :: "r"(dst), "l"(src), "r"(sz));
}
__device__ __forceinline__ void cp_commit() {
    asm volatile("cp.async.commit_group;\n");
}
__device__ __forceinline__ void cp_wait2() {
    asm volatile("cp.async.wait_group 2;\n");
}

__device__ __forceinline__ float tanha(float x) {
    float y;
    asm("tanh.approx.f32 %0, %1;" : "=f"(y) : "f"(x));
    return y;
}

__device__ __forceinline__ void ldsm4(uint32_t& r0, uint32_t& r1,
                                      uint32_t& r2, uint32_t& r3, uint32_t addr) {
    asm volatile("ldmatrix.sync.aligned.m8n8.x4.shared.b16 {%0,%1,%2,%3}, [%4];"
                 : "=r"(r0), "=r"(r1), "=r"(r2), "=r"(r3) : "r"(addr));
}

__device__ __forceinline__ void mma16816(float* c,
                                         uint32_t a0, uint32_t a1, uint32_t a2, uint32_t a3,
                                         uint32_t b0, uint32_t b1) {
    asm volatile(
        "mma.sync.aligned.m16n8k16.row.col.f32.f16.f16.f32 "
        "{%0,%1,%2,%3},{%4,%5,%6,%7},{%8,%9},{%0,%1,%2,%3};"
        : "+f"(c[0]), "+f"(c[1]), "+f"(c[2]), "+f"(c[3])
        : "r"(a0), "r"(a1), "r"(a2), "r"(a3), "r"(b0), "r"(b1));
}

// ---------------------------------------------------------------------------
// Pre-convert kernels (fp32 -> fp16)
// ---------------------------------------------------------------------------
__global__ __launch_bounds__(256)
void convW_kernel(const float4* __restrict__ W4) {
    int idx = blockIdx.x * 256 + threadIdx.x;       // 262144 float4s
    float4 v = W4[idx];
    __half2* o = reinterpret_cast<__half2*>(g_Wh);
    o[idx * 2]     = __floats2half2_rn(v.x, v.y);
    o[idx * 2 + 1] = __floats2half2_rn(v.z, v.w);
}

__global__ __launch_bounds__(256)
void convX_kernel(const float4* __restrict__ x4, const int* __restrict__ doc) {
    const int b = blockIdx.x;
    const int start = doc[2 * b];
    const int end   = doc[2 * b + 1];
    const int t = threadIdx.x;
    __half2* o = reinterpret_cast<__half2*>(g_xh);
    for (int s = start; s < end; s++) {
        size_t base = (size_t)(b * Sn + s) * (En / 4) + t;
        float4 v = x4[base];
        o[base * 2]     = __floats2half2_rn(v.x, v.y);
        o[base * 2 + 1] = __floats2half2_rn(v.z, v.w);
    }
}

// ---------------------------------------------------------------------------
// Kernel A: two bags per CTA — scores + softmax + out GEMV + keep_attention.
// ---------------------------------------------------------------------------
extern __shared__ char smem[];

__global__ __launch_bounds__(NTHR, 1)
void scores_kernel(const float4* __restrict__ x4,
                   const float* __restrict__ u,
                   const int* __restrict__ doc,
                   float* __restrict__ out) {
    const int b1   = blockIdx.x;            // bag 1
    const int b2   = blockIdx.x + NBLK;     // bag 2
    const int tid  = threadIdx.x;
    const int lane = tid & 31;
    const int wid  = tid >> 5;
    const int wm   = wid % WMN;       // subtile class (mod 3 within each bag)
    const int wn   = wid / WMN;       // cols [wn*32, wn*32+32)
    const int g    = lane >> 2;
    const int tg   = lane & 3;

    const int start1 = doc[2 * b1];
    const int len1   = doc[2 * b1 + 1] - start1;     // 1..96
    const int start2 = doc[2 * b2];
    const int len2   = doc[2 * b2 + 1] - start2;
    const int nmt1   = (len1 + 15) >> 4;             // 1..6
    const int nmt2   = (len2 + 15) >> 4;
    const int plen1  = nmt1 << 4;
    const int plen2  = nmt2 << 4;

    // 4 accumulator slots per warp: a=0,1 -> bag1 subtiles wm, wm+3
    //                               a=2,3 -> bag2 subtiles wm, wm+3
    bool act[4];
    int  rowb[4];
    act[0] = (wm < nmt1);      rowb[0] = wm * 16;
    act[1] = (wm + 3 < nmt1);  rowb[1] = (wm + 3) * 16;
    act[2] = (wm < nmt2);      rowb[2] = 96 + wm * 16;
    act[3] = (wm + 3 < nmt2);  rowb[3] = 96 + (wm + 3) * 16;

    const uint32_t smem_u32 = (uint32_t)__cvta_generic_to_shared(smem);
    float* u_s    = reinterpret_cast<float*>(smem + OFF_U);
    float* s_part = reinterpret_cast<float*>(smem + OFF_SP);
    float* attn_s = reinterpret_cast<float*>(smem + OFF_AT);

    for (int i = tid; i < En; i += NTHR) u_s[i] = u[i];
    for (int i = tid; i < MT * WNN; i += NTHR) s_part[i] = 0.0f;

    // fill-lane constants
    const int fa_m = tid >> 3;        // 0..47 base row (+48*i)
    const int fa_c = tid & 7;

    auto fill = [&](int t) {
        const int fc = t >> 4;
        const int k0 = (t & 15) * KT;
        const uint32_t aBase = smem_u32 + (t % STAGES) * STG_B;
        const uint32_t bBase = aBase + A_TILE_B;
        #pragma unroll
        for (int i = 0; i < 4; i++) {             // 1536 A chunks / 384 thr
            int m = fa_m + i * 48;                // 0..191
            int mloc  = (m >= 96) ? (m - 96) : m;
            int bagst = (m >= 96) ? start2 : start1;
            int bagb  = (m >= 96) ? b2 : b1;
            int pl    = (m >= 96) ? plen2 : plen1;
            int ln    = (m >= 96) ? len2 : len1;
            if (mloc < pl) {                      // rows >= plen never read
                uint32_t dst = aBase + m * 128 + ((fa_c ^ (m & 7)) << 4);
                const __half* src = g_xh +
                    (size_t)(bagb * Sn + bagst + mloc) * En + k0 + fa_c * 8;
                cp16(dst, src, mloc < ln);        // zfill pads [len, plen)
            }
        }
        #pragma unroll
        for (int i = 0; i < 3; i++) {             // 1024 B chunks / 384 thr
            int ch = tid + i * NTHR;
            if (ch < NT * 8) {
                int n = ch >> 3, c = ch & 7;
                uint32_t dst = bBase + n * 128 + ((c ^ (n & 7)) << 4);
                const __half* src = g_Wh + (size_t)(fc * NT + n) * En + k0 + c * 8;
                cp16(dst, src, true);
            }
        }
        cp_commit();
    };

    float acc[4][4][4];
    #pragma unroll
    for (int a = 0; a < 4; a++)
        #pragma unroll
        for (int j = 0; j < 4; j++)
            #pragma unroll
            for (int i = 0; i < 4; i++) acc[a][j][i] = 0.0f;
    float sacc[4][2] = {{0.f,0.f},{0.f,0.f},{0.f,0.f},{0.f,0.f}};

    // ldmatrix lane-address components
    const int a_row   = (lane & 15);
    const int a_choff = (lane >> 4);
    const int b_rowin = (lane & 7) + ((lane >> 4) << 3);
    const int b_choff = ((lane >> 3) & 1);

    // prologue: stage tiles 0..2
    fill(0);
    fill(1);
    fill(2);

    for (int t = 0; t < TILES; t++) {
        cp_wait2();          // tile t landed (<=2 groups pending: t+1, t+2)
        __syncthreads();     // all fills visible; stage (t-1)%4 reads done
        if (t + 3 < TILES) fill(t + 3);
        else cp_commit();    // keep group accounting uniform

        const uint32_t aBase = smem_u32 + (t % STAGES) * STG_B;
        const uint32_t bBase = aBase + A_TILE_B;

        #pragma unroll
        for (int ks = 0; ks < 4; ks++) {
            uint32_t bf[2][4];
            #pragma unroll
            for (int jp = 0; jp < 2; jp++) {
                int nrow = wn * 32 + jp * 16 + b_rowin;
                int chv = 2 * ks + b_choff;
                uint32_t addr = bBase + nrow * 128 + ((chv ^ (nrow & 7)) << 4);
                ldsm4(bf[jp][0], bf[jp][1], bf[jp][2], bf[jp][3], addr);
            }
            #pragma unroll
            for (int a = 0; a < 4; a++) {
                if (act[a]) {
                    uint32_t af[4];
                    int row = rowb[a] + a_row;
                    int chv = 2 * ks + a_choff;
                    uint32_t addr = aBase + row * 128 + ((chv ^ (row & 7)) << 4);
                    ldsm4(af[0], af[1], af[2], af[3], addr);
                    #pragma unroll
                    for (int j = 0; j < 4; j++) {
                        mma16816(acc[a][j], af[0], af[1], af[2], af[3],
                                 bf[j >> 1][(j & 1) * 2], bf[j >> 1][(j & 1) * 2 + 1]);
                    }
                }
            }
        }

        if ((t & 15) == 15) {
            const int fc = t >> 4;
            #pragma unroll
            for (int a = 0; a < 4; a++) {
                if (act[a]) {
                    #pragma unroll
                    for (int j = 0; j < 4; j++) {
                        int f = fc * NT + wn * 32 + j * 8 + 2 * tg;
                        float u0 = u_s[f], u1 = u_s[f + 1];
                        sacc[a][0] += tanha(acc[a][j][0]) * u0 + tanha(acc[a][j][1]) * u1;
                        sacc[a][1] += tanha(acc[a][j][2]) * u0 + tanha(acc[a][j][3]) * u1;
                        acc[a][j][0] = 0.f; acc[a][j][1] = 0.f;
                        acc[a][j][2] = 0.f; acc[a][j][3] = 0.f;
                    }
                }
            }
        }
    }

    // deterministic tg-reduction, write partials
    #pragma unroll
    for (int a = 0; a < 4; a++) {
        #pragma unroll
        for (int rg = 0; rg < 2; rg++) {
            float v = sacc[a][rg];
            v += __shfl_xor_sync(0xffffffffu, v, 1);
            v += __shfl_xor_sync(0xffffffffu, v, 2);
            if (act[a] && tg == 0) {
                int row = rowb[a] + rg * 8 + g;
                s_part[row * WNN + wn] = v;
            }
        }
    }
    __syncthreads();

    // softmax — warp 0: bag1 (rows 0..95), warp 1: bag2 (rows 96..191)
    if (wid < 2) {
        const int roff = wid * 96;
        const int ln   = wid ? len2 : len1;
        float v[3];
        #pragma unroll
        for (int i = 0; i < 3; i++) {
            int r = lane + 32 * i;
            float sv = s_part[(roff + r) * WNN + 0] + s_part[(roff + r) * WNN + 1] +
                       s_part[(roff + r) * WNN + 2] + s_part[(roff + r) * WNN + 3];
            v[i] = (r < ln) ? sv : -3.0e38f;
        }
        float mx = fmaxf(v[0], fmaxf(v[1], v[2]));
        #pragma unroll
        for (int o = 16; o > 0; o >>= 1)
            mx = fmaxf(mx, __shfl_xor_sync(0xffffffffu, mx, o));
        float e[3];
        float ssum = 0.0f;
        #pragma unroll
        for (int i = 0; i < 3; i++) {
            int r = lane + 32 * i;
            e[i] = (r < ln) ? __expf(v[i] - mx) : 0.0f;
            ssum += e[i];
        }
        #pragma unroll
        for (int o = 16; o > 0; o >>= 1)
            ssum += __shfl_xor_sync(0xffffffffu, ssum, o);
        float inv = 1.0f / ssum;
        #pragma unroll
        for (int i = 0; i < 3; i++) {
            int r = lane + 32 * i;
            attn_s[roff + r] = (r < ln) ? e[i] * inv : 0.0f;
        }
    }
    __syncthreads();

    // fused out GEMV for both bags (256 of 384 threads per bag)
    if (tid < 256) {
        #pragma unroll
        for (int bag = 0; bag < 2; bag++) {
            const int bb    = bag ? b2 : b1;
            const int st    = bag ? start2 : start1;
            const int ln    = bag ? len2 : len1;
            const float* at = attn_s + bag * 96;
            const float4* xb = x4 + (size_t)(bb * Sn + st) * (En / 4);
            float4 a0 = make_float4(0.f, 0.f, 0.f, 0.f);
            float4 a1 = make_float4(0.f, 0.f, 0.f, 0.f);
            int s = 0;
            for (; s + 2 <= ln; s += 2) {
                float w0 = at[s], w1 = at[s + 1];
                float4 v0 = xb[(size_t)s * (En / 4) + tid];
                float4 v1 = xb[(size_t)(s + 1) * (En / 4) + tid];
                a0.x += w0 * v0.x; a0.y += w0 * v0.y; a0.z += w0 * v0.z; a0.w += w0 * v0.w;
                a1.x += w1 * v1.x; a1.y += w1 * v1.y; a1.z += w1 * v1.z; a1.w += w1 * v1.w;
            }
            if (s < ln) {
                float w0 = at[s];
                float4 v0 = xb[(size_t)s * (En / 4) + tid];
                a0.x += w0 * v0.x; a0.y += w0 * v0.y; a0.z += w0 * v0.z; a0.w += w0 * v0.w;
            }
            a0.x += a1.x; a0.y += a1.y; a0.z += a1.z; a0.w += a1.w;
            reinterpret_cast<float4*>(out)[(size_t)bb * (En / 4) + tid] = a0;
        }
    }

    // fused keep_attention: bag2 of the last CTA is batch 255
    if (b2 == Bn - 1 && tid < Sn) {
        int r = tid - start2;
        out[(size_t)Bn * En + tid] = (r >= 0 && r < len2) ? attn_s[96 + r] : 0.0f;
    }
}

// ---------------------------------------------------------------------------
extern "C" void kernel_launch(void* const* d_in, const int* in_sizes, int n_in,
                              void* d_out, int out_size) {
    const float* x   = (const float*)d_in[0];
    const float* W   = (const float*)d_in[1];
    const float* u   = (const float*)d_in[2];
    const int*   doc = (const int*)d_in[3];
    float* out = (float*)d_out;

    convW_kernel<<<1024, 256>>>((const float4*)W);
    convX_kernel<<<Bn, 256>>>((const float4*)x, doc);

    cudaFuncSetAttribute(scores_kernel,
                         cudaFuncAttributeMaxDynamicSharedMemorySize, SMEM_TOTAL);
    scores_kernel<<<NBLK, NTHR, SMEM_TOTAL>>>((const float4*)x, u, doc, out);
}

// round 8
// speedup vs baseline: 1.0904x; 1.0904x over previous
#include <cuda_runtime.h>
#include <cuda_fp16.h>
#include <cstdint>
#include <cstddef>

#define Bn 256
#define Sn 128
#define En 1024

constexpr int MT   = 96;
constexpr int NT   = 128;           // f-columns per chunk
constexpr int KT   = 128;           // K halfs per tile (256B rows)
constexpr int NFC  = En / NT;       // 8
constexpr int NKT  = En / KT;       // 8
constexpr int TILES = NFC * NKT;    // 64
constexpr int NTHR = 256;           // 8 warps: 2 (M, interleaved) x 4 (N, 32 cols)
constexpr int WMN  = 2;
constexpr int WNN  = 4;
constexpr int STAGES = 2;

constexpr int A_TILE_B = MT * KT * 2;   // 24576
constexpr int B_TILE_B = NT * KT * 2;   // 32768
constexpr int STG_B    = A_TILE_B + B_TILE_B;     // 57344
constexpr int SMEM_TOTAL = STAGES * STG_B;        // 114688 = 112KB -> 2 CTAs/SM
// s_part / attn_s alias into stage 0 (only touched after the mainloop;
// the last tile (63, odd) reads stage 1, so no overlap hazard).
constexpr int OFF_SP = 0;                          // 96*4 floats = 1536B
constexpr int OFF_AT = OFF_SP + MT * WNN * 4;      // 96 floats

// device-global scratch (allocations are forbidden)
__device__ __half g_Wh[En * En];
__device__ __half g_xh[Bn * Sn * En];

// ---------------------------------------------------------------------------
__device__ __forceinline__ void cp16(uint32_t dst, const void* src, bool pred) {
    int sz = pred ? 16 : 0;
    asm volatile("cp.async.cg.shared.global [%0], [%1], 16, %2;\n"
                 :: "r"(dst), "l"(src), "r"(sz));
}
__device__ __forceinline__ void cp_commit() {
    asm volatile("cp.async.commit_group;\n");
}
__device__ __forceinline__ void cp_wait0() {
    asm volatile("cp.async.wait_group 0;\n");
}

__device__ __forceinline__ float tanha(float x) {
    float y;
    asm("tanh.approx.f32 %0, %1;" : "=f"(y) : "f"(x));
    return y;
}

__device__ __forceinline__ void ldsm4(uint32_t& r0, uint32_t& r1,
                                      uint32_t& r2, uint32_t& r3, uint32_t addr) {
    asm volatile("ldmatrix.sync.aligned.m8n8.x4.shared.b16 {%0,%1,%2,%3}, [%4];"
                 : "=r"(r0), "=r"(r1), "=r"(r2), "=r"(r3) : "r"(addr));
}

__device__ __forceinline__ void mma16816(float* c,
                                         uint32_t a0, uint32_t a1, uint32_t a2, uint32_t a3,
                                         uint32_t b0, uint32_t b1) {
    asm volatile(
        "mma.sync.aligned.m16n8k16.row.col.f32.f16.f16.f32 "
        "{%0,%1,%2,%3},{%4,%5,%6,%7},{%8,%9},{%0,%1,%2,%3};"
        : "+f"(c[0]), "+f"(c[1]), "+f"(c[2]), "+f"(c[3])
        : "r"(a0), "r"(a1), "r"(a2), "r"(a3), "r"(b0), "r"(b1));
}

// ---------------------------------------------------------------------------
// Merged pre-convert kernel (fp32 -> fp16): blocks [0,1024) do W, rest do x.
// ---------------------------------------------------------------------------
__global__ __launch_bounds__(256)
void conv_kernel(const float4* __restrict__ W4,
                 const float4* __restrict__ x4,
                 const int* __restrict__ doc) {
    const int bx = blockIdx.x;
    const int t  = threadIdx.x;
    if (bx < 1024) {
        int idx = bx * 256 + t;                 // 262144 float4s of W
        float4 v = W4[idx];
        __half2* o = reinterpret_cast<__half2*>(g_Wh);
        o[idx * 2]     = __floats2half2_rn(v.x, v.y);
        o[idx * 2 + 1] = __floats2half2_rn(v.z, v.w);
    } else {
        const int b = bx - 1024;
        const int start = doc[2 * b];
        const int end   = doc[2 * b + 1];
        __half2* o = reinterpret_cast<__half2*>(g_xh);
        for (int s = start; s < end; s++) {
            size_t base = (size_t)(b * Sn + s) * (En / 4) + t;
            float4 v = x4[base];
            o[base * 2]     = __floats2half2_rn(v.x, v.y);
            o[base * 2 + 1] = __floats2half2_rn(v.z, v.w);
        }
    }
}

// ---------------------------------------------------------------------------
// Main kernel: fused scores + softmax + out GEMV + keep_attention.
// ---------------------------------------------------------------------------
extern __shared__ char smem[];

__global__ __launch_bounds__(NTHR, 2)
void scores_kernel(const float* __restrict__ u,
                   const int* __restrict__ doc,
                   float* __restrict__ out) {
    const int b    = blockIdx.x;
    const int tid  = threadIdx.x;
    const int lane = tid & 31;
    const int wid  = tid >> 5;
    const int wm   = wid % WMN;       // subtiles st with st%2==wm (interleaved)
    const int wn   = wid / WMN;       // cols [wn*32, wn*32+32)
    const int g    = lane >> 2;
    const int tg   = lane & 3;

    const int start = doc[2 * b];
    const int len   = doc[2 * b + 1] - start;    // 1..96
    const int nmt   = (len + 15) >> 4;           // active 16-row subtiles (1..6)
    const int plen  = nmt << 4;                  // padded rows ever read
    const int nms   = (nmt + 1 - wm) >> 1;       // this warp's active subtiles (0..3)

    const uint32_t smem_u32 = (uint32_t)__cvta_generic_to_shared(smem);
    float* s_part = reinterpret_cast<float*>(smem + OFF_SP);
    float* attn_s = reinterpret_cast<float*>(smem + OFF_AT);

    // fill-lane constants: 16 chunks of 16B per 256B row
    const int fa_m = tid >> 4;        // 0..15 base row (+16*i)
    const int fa_c = tid & 15;        // chunk in row

    auto fill = [&](int t) {
        const int fc = t >> 3;
        const int k0 = (t & 7) * KT;
        const uint32_t aBase = smem_u32 + (t & 1) * STG_B;
        const uint32_t bBase = aBase + A_TILE_B;
        #pragma unroll
        for (int i = 0; i < 6; i++) {           // 1536 A chunks / 256 thr
            int m = fa_m + i * 16;
            if (m < plen) {                     // rows >= plen never read
                uint32_t dst = aBase + m * 256 + ((fa_c ^ (m & 7)) << 4);
                const __half* src = g_xh + (size_t)(b * Sn + start + m) * En + k0 + fa_c * 8;
                cp16(dst, src, m < len);        // zfill pads [len, plen)
            }
        }
        #pragma unroll
        for (int i = 0; i < 8; i++) {           // 2048 B chunks / 256 thr
            int n = fa_m + i * 16;
            uint32_t dst = bBase + n * 256 + ((fa_c ^ (n & 7)) << 4);
            const __half* src = g_Wh + (size_t)(fc * NT + n) * En + k0 + fa_c * 8;
            cp16(dst, src, true);
        }
        cp_commit();
    };

    float acc[3][4][4];
    #pragma unroll
    for (int ms = 0; ms < 3; ms++)
        #pragma unroll
        for (int j = 0; j < 4; j++)
            #pragma unroll
            for (int i = 0; i < 4; i++) acc[ms][j][i] = 0.0f;
    float sacc[3][2] = {{0.f,0.f},{0.f,0.f},{0.f,0.f}};

    // ldmatrix lane-address components
    const int a_row   = (lane & 15);
    const int a_choff = (lane >> 4);
    const int b_rowin = (lane & 7) + ((lane >> 4) << 3);
    const int b_choff = ((lane >> 3) & 1);

    fill(0);

    for (int t = 0; t < TILES; t++) {
        cp_wait0();          // my fills for t done
        __syncthreads();     // all threads' fills visible; prior-stage reads done
        if (t + 1 < TILES) fill(t + 1);

        const uint32_t aBase = smem_u32 + (t & 1) * STG_B;
        const uint32_t bBase = aBase + A_TILE_B;

        if (nms > 0) {
            #pragma unroll
            for (int ks = 0; ks < 8; ks++) {
                uint32_t af[3][4];
                #pragma unroll
                for (int ms = 0; ms < 3; ms++) {
                    if (ms < nms) {
                        int row = (2 * ms + wm) * 16 + a_row;
                        int chv = 2 * ks + a_choff;
                        uint32_t addr = aBase + row * 256 + ((chv ^ (row & 7)) << 4);
                        ldsm4(af[ms][0], af[ms][1], af[ms][2], af[ms][3], addr);
                    }
                }
                uint32_t bf[2][4];
                #pragma unroll
                for (int jp = 0; jp < 2; jp++) {
                    int nrow = wn * 32 + jp * 16 + b_rowin;
                    int chv = 2 * ks + b_choff;
                    uint32_t addr = bBase + nrow * 256 + ((chv ^ (nrow & 7)) << 4);
                    ldsm4(bf[jp][0], bf[jp][1], bf[jp][2], bf[jp][3], addr);
                }
                #pragma unroll
                for (int ms = 0; ms < 3; ms++) {
                    if (ms < nms) {
                        #pragma unroll
                        for (int j = 0; j < 4; j++) {
                            mma16816(acc[ms][j],
                                     af[ms][0], af[ms][1], af[ms][2], af[ms][3],
                                     bf[j >> 1][(j & 1) * 2], bf[j >> 1][(j & 1) * 2 + 1]);
                        }
                    }
                }
            }
        }

        if ((t & 7) == 7) {
            // f-chunk epilogue: scores += tanh(z) * u  (u via __ldg, L1-hot)
            const int fc = t >> 3;
            #pragma unroll
            for (int ms = 0; ms < 3; ms++) {
                if (ms < nms) {
                    #pragma unroll
                    for (int j = 0; j < 4; j++) {
                        int f = fc * NT + wn * 32 + j * 8 + 2 * tg;
                        float u0 = __ldg(u + f), u1 = __ldg(u + f + 1);
                        sacc[ms][0] += tanha(acc[ms][j][0]) * u0 + tanha(acc[ms][j][1]) * u1;
                        sacc[ms][1] += tanha(acc[ms][j][2]) * u0 + tanha(acc[ms][j][3]) * u1;
                        acc[ms][j][0] = 0.f; acc[ms][j][1] = 0.f;
                        acc[ms][j][2] = 0.f; acc[ms][j][3] = 0.f;
                    }
                }
            }
        }
    }

    // deterministic tg-reduction, write partials (aliased into stage 0;
    // last tile read stage 1, and each thread finished its reads already)
    #pragma unroll
    for (int ms = 0; ms < 3; ms++) {
        #pragma unroll
        for (int rg = 0; rg < 2; rg++) {
            float v = sacc[ms][rg];
            v += __shfl_xor_sync(0xffffffffu, v, 1);
            v += __shfl_xor_sync(0xffffffffu, v, 2);
            if (ms < nms && tg == 0) {
                int row = (2 * ms + wm) * 16 + rg * 8 + g;
                s_part[row * WNN + wn] = v;
            }
        }
    }
    __syncthreads();

    // softmax over the bag — warp 0 (deterministic); result -> attn_s[0..95]
    // (rows >= plen read uninitialized s_part but are masked before use)
    if (wid == 0) {
        float v[3];
        #pragma unroll
        for (int i = 0; i < 3; i++) {
            int r = lane + 32 * i;
            float sv = s_part[r * WNN + 0] + s_part[r * WNN + 1] +
                       s_part[r * WNN + 2] + s_part[r * WNN + 3];
            v[i] = (r < len) ? sv : -3.0e38f;
        }
        float mx = fmaxf(v[0], fmaxf(v[1], v[2]));
        #pragma unroll
        for (int o = 16; o > 0; o >>= 1)
            mx = fmaxf(mx, __shfl_xor_sync(0xffffffffu, mx, o));
        float e[3];
        float ssum = 0.0f;
        #pragma unroll
        for (int i = 0; i < 3; i++) {
            int r = lane + 32 * i;
            e[i] = (r < len) ? __expf(v[i] - mx) : 0.0f;
            ssum += e[i];
        }
        #pragma unroll
        for (int o = 16; o > 0; o >>= 1)
            ssum += __shfl_xor_sync(0xffffffffu, ssum, o);
        float inv = 1.0f / ssum;
        #pragma unroll
        for (int i = 0; i < 3; i++) {
            int r = lane + 32 * i;
            attn_s[r] = (r < len) ? e[i] * inv : 0.0f;
        }
    }
    __syncthreads();

    // fused out GEMV from fp16 x: out[b,:] = sum_s attn_s[s] * xh[b,start+s,:]
    {
        const uint2* xb = reinterpret_cast<const uint2*>(
            g_xh + (size_t)(b * Sn + start) * En);      // 4 halfs per uint2
        float4 a0 = make_float4(0.f, 0.f, 0.f, 0.f);
        float4 a1 = make_float4(0.f, 0.f, 0.f, 0.f);
        int s = 0;
        for (; s + 2 <= len; s += 2) {
            float w0 = attn_s[s], w1 = attn_s[s + 1];
            uint2 v0 = xb[(size_t)s * (En / 4) + tid];
            uint2 v1 = xb[(size_t)(s + 1) * (En / 4) + tid];
            float2 p0 = __half22float2(*reinterpret_cast<__half2*>(&v0.x));
            float2 p1 = __half22float2(*reinterpret_cast<__half2*>(&v0.y));
            float2 q0 = __half22float2(*reinterpret_cast<__half2*>(&v1.x));
            float2 q1 = __half22float2(*reinterpret_cast<__half2*>(&v1.y));
            a0.x += w0 * p0.x; a0.y += w0 * p0.y; a0.z += w0 * p1.x; a0.w += w0 * p1.y;
            a1.x += w1 * q0.x; a1.y += w1 * q0.y; a1.z += w1 * q1.x; a1.w += w1 * q1.y;
        }
        if (s < len) {
            float w0 = attn_s[s];
            uint2 v0 = xb[(size_t)s * (En / 4) + tid];
            float2 p0 = __half22float2(*reinterpret_cast<__half2*>(&v0.x));
            float2 p1 = __half22float2(*reinterpret_cast<__half2*>(&v0.y));
            a0.x += w0 * p0.x; a0.y += w0 * p0.y; a0.z += w0 * p1.x; a0.w += w0 * p1.y;
        }
        a0.x += a1.x; a0.y += a1.y; a0.z += a1.z; a0.w += a1.w;
        reinterpret_cast<float4*>(out)[(size_t)b * (En / 4) + tid] = a0;
    }

    // fused keep_attention (last batch only): zeros outside the bag
    if (b == Bn - 1 && tid < Sn) {
        int r = tid - start;
        out[(size_t)Bn * En + tid] = (r >= 0 && r < len) ? attn_s[r] : 0.0f;
    }
}

// ---------------------------------------------------------------------------
extern "C" void kernel_launch(void* const* d_in, const int* in_sizes, int n_in,
                              void* d_out, int out_size) {
    const float* x   = (const float*)d_in[0];
    const float* W   = (const float*)d_in[1];
    const float* u   = (const float*)d_in[2];
    const int*   doc = (const int*)d_in[3];
    float* out = (float*)d_out;

    conv_kernel<<<1024 + Bn, 256>>>((const float4*)W, (const float4*)x, doc);

    cudaFuncSetAttribute(scores_kernel,
                         cudaFuncAttributeMaxDynamicSharedMemorySize, SMEM_TOTAL);
    scores_kernel<<<Bn, NTHR, SMEM_TOTAL>>>(u, doc, out);
}

// round 9
// speedup vs baseline: 1.1469x; 1.0518x over previous
#include <cuda_runtime.h>
#include <cuda_fp16.h>
#include <cstdint>
#include <cstddef>

#define Bn 256
#define Sn 128
#define En 1024

constexpr int MT   = 96;
constexpr int NT   = 128;           // f-columns per chunk
constexpr int KT   = 128;           // K halfs per tile (256B rows)
constexpr int NFC  = En / NT;       // 8
constexpr int NKT  = En / KT;       // 8
constexpr int TILES = NFC * NKT;    // 64
constexpr int NTHR = 256;           // 8 warps: 2 (M, interleaved) x 4 (N, 32 cols)
constexpr int WMN  = 2;
constexpr int WNN  = 4;
constexpr int STAGES = 2;

constexpr int A_TILE_B = MT * KT * 2;   // 24576
constexpr int B_TILE_B = NT * KT * 2;   // 32768
constexpr int STG_B    = A_TILE_B + B_TILE_B;     // 57344
constexpr int SMEM_TOTAL = STAGES * STG_B;        // 114688 -> 2 CTAs/SM
// s_part / attn_s alias into stage 0 (only touched after the mainloop;
// the last tile (63, odd) reads stage 1, so no overlap hazard).
constexpr int OFF_SP = 0;
constexpr int OFF_AT = OFF_SP + MT * WNN * 4;

// device-global scratch (allocations are forbidden)
__device__ __half g_Wh[En * En];
__device__ __half g_xh[Bn * Sn * En];

// ---------------------------------------------------------------------------
__device__ __forceinline__ void cp16(uint32_t dst, const void* src, bool pred) {
    int sz = pred ? 16 : 0;
    asm volatile("cp.async.cg.shared.global [%0], [%1], 16, %2;\n"
                 :: "r"(dst), "l"(src), "r"(sz));
}
__device__ __forceinline__ void cp_commit() {
    asm volatile("cp.async.commit_group;\n");
}
__device__ __forceinline__ void cp_wait0() {
    asm volatile("cp.async.wait_group 0;\n");
}

__device__ __forceinline__ float tanha(float x) {
    float y;
    asm("tanh.approx.f32 %0, %1;" : "=f"(y) : "f"(x));
    return y;
}

__device__ __forceinline__ void ldsm4(uint32_t& r0, uint32_t& r1,
                                      uint32_t& r2, uint32_t& r3, uint32_t addr) {
    asm volatile("ldmatrix.sync.aligned.m8n8.x4.shared.b16 {%0,%1,%2,%3}, [%4];"
                 : "=r"(r0), "=r"(r1), "=r"(r2), "=r"(r3) : "r"(addr));
}

__device__ __forceinline__ void mma16816(float* c,
                                         uint32_t a0, uint32_t a1, uint32_t a2, uint32_t a3,
                                         uint32_t b0, uint32_t b1) {
    asm volatile(
        "mma.sync.aligned.m16n8k16.row.col.f32.f16.f16.f32 "
        "{%0,%1,%2,%3},{%4,%5,%6,%7},{%8,%9},{%0,%1,%2,%3};"
        : "+f"(c[0]), "+f"(c[1]), "+f"(c[2]), "+f"(c[3])
        : "r"(a0), "r"(a1), "r"(a2), "r"(a3), "r"(b0), "r"(b1));
}

// ---------------------------------------------------------------------------
// Merged pre-convert kernel (fp32 -> fp16): blocks [0,1024) do W, rest do x.
// ---------------------------------------------------------------------------
__global__ __launch_bounds__(256)
void conv_kernel(const float4* __restrict__ W4,
                 const float4* __restrict__ x4,
                 const int* __restrict__ doc) {
    const int bx = blockIdx.x;
    const int t  = threadIdx.x;
    if (bx < 1024) {
        int idx = bx * 256 + t;
        float4 v = W4[idx];
        __half2* o = reinterpret_cast<__half2*>(g_Wh);
        o[idx * 2]     = __floats2half2_rn(v.x, v.y);
        o[idx * 2 + 1] = __floats2half2_rn(v.z, v.w);
    } else {
        const int b = bx - 1024;
        const int start = doc[2 * b];
        const int end   = doc[2 * b + 1];
        __half2* o = reinterpret_cast<__half2*>(g_xh);
        for (int s = start; s < end; s++) {
            size_t base = (size_t)(b * Sn + s) * (En / 4) + t;
            float4 v = x4[base];
            o[base * 2]     = __floats2half2_rn(v.x, v.y);
            o[base * 2 + 1] = __floats2half2_rn(v.z, v.w);
        }
    }
}

// ---------------------------------------------------------------------------
// Main kernel: fused scores + softmax + out GEMV + keep_attention.
// Fills for tile t+1 are interleaved into tile t's ks loop (smooth LSU load).
// ---------------------------------------------------------------------------
extern __shared__ char smem[];

__global__ __launch_bounds__(NTHR, 2)
void scores_kernel(const float* __restrict__ u,
                   const int* __restrict__ doc,
                   float* __restrict__ out) {
    const int b    = blockIdx.x;
    const int tid  = threadIdx.x;
    const int lane = tid & 31;
    const int wid  = tid >> 5;
    const int wm   = wid % WMN;
    const int wn   = wid / WMN;
    const int g    = lane >> 2;
    const int tg   = lane & 3;

    const int start = doc[2 * b];
    const int len   = doc[2 * b + 1] - start;    // 1..96
    const int nmt   = (len + 15) >> 4;           // active 16-row subtiles (1..6)
    const int plen  = nmt << 4;
    const int nms   = (nmt + 1 - wm) >> 1;       // this warp's subtiles (0..3)

    const uint32_t smem_u32 = (uint32_t)__cvta_generic_to_shared(smem);
    float* s_part = reinterpret_cast<float*>(smem + OFF_SP);
    float* attn_s = reinterpret_cast<float*>(smem + OFF_AT);

    const int fa_m = tid >> 4;        // 0..15 base row (+16*i)
    const int fa_c = tid & 15;        // 16B chunk in 256B row

    // A-source row pointer component (row band fa_m + i*16)
    const __half* xrow = g_xh + (size_t)(b * Sn + start) * En + fa_c * 8;

    // full fill of one tile (prologue only)
    auto fill_full = [&](int t) {
        const int fc = t >> 3;
        const int k0 = (t & 7) * KT;
        const uint32_t aBase = smem_u32 + (t & 1) * STG_B;
        const uint32_t bBase = aBase + A_TILE_B;
        #pragma unroll
        for (int i = 0; i < 6; i++) {
            int m = fa_m + i * 16;
            if (m < plen) {
                uint32_t dst = aBase + m * 256 + ((fa_c ^ (m & 7)) << 4);
                cp16(dst, xrow + (size_t)m * En + k0, m < len);
            }
        }
        #pragma unroll
        for (int i = 0; i < 8; i++) {
            int n = fa_m + i * 16;
            uint32_t dst = bBase + n * 256 + ((fa_c ^ (n & 7)) << 4);
            cp16(dst, g_Wh + (size_t)(fc * NT + n) * En + k0 + fa_c * 8, true);
        }
        cp_commit();
    };

    float acc[3][4][4];
    #pragma unroll
    for (int ms = 0; ms < 3; ms++)
        #pragma unroll
        for (int j = 0; j < 4; j++)
            #pragma unroll
            for (int i = 0; i < 4; i++) acc[ms][j][i] = 0.0f;
    float sacc[3][2] = {{0.f,0.f},{0.f,0.f},{0.f,0.f}};

    const int a_row   = (lane & 15);
    const int a_choff = (lane >> 4);
    const int b_rowin = (lane & 7) + ((lane >> 4) << 3);
    const int b_choff = ((lane >> 3) & 1);

    fill_full(0);

    for (int fc = 0; fc < NFC; fc++) {
        for (int k = 0; k < NKT; k++) {
            const int t = fc * NKT + k;
            cp_wait0();          // tile t's fills landed (mine)
            __syncthreads();     // all threads' fills visible; prior reads done

            const uint32_t aBase = smem_u32 + (t & 1) * STG_B;
            const uint32_t bBase = aBase + A_TILE_B;

            // interleaved fill target (tile t+1)
            const bool have_next = (t + 1 < TILES);
            const int  nfc = (t + 1) >> 3;
            const int  nk0 = ((t + 1) & 7) * KT;
            const uint32_t naBase = smem_u32 + ((t + 1) & 1) * STG_B;
            const uint32_t nbBase = naBase + A_TILE_B;

            #pragma unroll
            for (int ks = 0; ks < 8; ks++) {
                // ---- interleave: ~2 cp.async of tile t+1 per ks step ----
                if (have_next) {
                    if (ks < 6) {
                        int m = fa_m + ks * 16;
                        if (m < plen) {
                            uint32_t dst = naBase + m * 256 + ((fa_c ^ (m & 7)) << 4);
                            cp16(dst, xrow + (size_t)m * En + nk0, m < len);
                        }
                    }
                    {
                        int n = fa_m + ks * 16;
                        uint32_t dst = nbBase + n * 256 + ((fa_c ^ (n & 7)) << 4);
                        cp16(dst, g_Wh + (size_t)(nfc * NT + n) * En + nk0 + fa_c * 8, true);
                    }
                }

                // ---- compute ----
                uint32_t af[3][4];
                #pragma unroll
                for (int ms = 0; ms < 3; ms++) {
                    if (ms < nms) {
                        int row = (2 * ms + wm) * 16 + a_row;
                        int chv = 2 * ks + a_choff;
                        uint32_t addr = aBase + row * 256 + ((chv ^ (row & 7)) << 4);
                        ldsm4(af[ms][0], af[ms][1], af[ms][2], af[ms][3], addr);
                    }
                }
                uint32_t bf[2][4];
                #pragma unroll
                for (int jp = 0; jp < 2; jp++) {
                    int nrow = wn * 32 + jp * 16 + b_rowin;
                    int chv = 2 * ks + b_choff;
                    uint32_t addr = bBase + nrow * 256 + ((chv ^ (nrow & 7)) << 4);
                    ldsm4(bf[jp][0], bf[jp][1], bf[jp][2], bf[jp][3], addr);
                }
                #pragma unroll
                for (int ms = 0; ms < 3; ms++) {
                    if (ms < nms) {
                        #pragma unroll
                        for (int j = 0; j < 4; j++) {
                            mma16816(acc[ms][j],
                                     af[ms][0], af[ms][1], af[ms][2], af[ms][3],
                                     bf[j >> 1][(j & 1) * 2], bf[j >> 1][(j & 1) * 2 + 1]);
                        }
                    }
                }
            }
            cp_commit();         // close tile t+1's fill group
        }

        // f-chunk epilogue: scores += tanh(z) * u  (u via __ldg, L1-hot)
        #pragma unroll
        for (int ms = 0; ms < 3; ms++) {
            if (ms < nms) {
                #pragma unroll
                for (int j = 0; j < 4; j++) {
                    int f = fc * NT + wn * 32 + j * 8 + 2 * tg;
                    float u0 = __ldg(u + f), u1 = __ldg(u + f + 1);
                    sacc[ms][0] += tanha(acc[ms][j][0]) * u0 + tanha(acc[ms][j][1]) * u1;
                    sacc[ms][1] += tanha(acc[ms][j][2]) * u0 + tanha(acc[ms][j][3]) * u1;
                    acc[ms][j][0] = 0.f; acc[ms][j][1] = 0.f;
                    acc[ms][j][2] = 0.f; acc[ms][j][3] = 0.f;
                }
            }
        }
    }

    // deterministic tg-reduction, write partials (aliased into stage 0;
    // the final tile (63) read stage 1, so no hazard)
    #pragma unroll
    for (int ms = 0; ms < 3; ms++) {
        #pragma unroll
        for (int rg = 0; rg < 2; rg++) {
            float v = sacc[ms][rg];
            v += __shfl_xor_sync(0xffffffffu, v, 1);
            v += __shfl_xor_sync(0xffffffffu, v, 2);
            if (ms < nms && tg == 0) {
                int row = (2 * ms + wm) * 16 + rg * 8 + g;
                s_part[row * WNN + wn] = v;
            }
        }
    }
    __syncthreads();

    // softmax over the bag — warp 0 (deterministic); result -> attn_s[0..95]
    if (wid == 0) {
        float v[3];
        #pragma unroll
        for (int i = 0; i < 3; i++) {
            int r = lane + 32 * i;
            float sv = s_part[r * WNN + 0] + s_part[r * WNN + 1] +
                       s_part[r * WNN + 2] + s_part[r * WNN + 3];
            v[i] = (r < len) ? sv : -3.0e38f;
        }
        float mx = fmaxf(v[0], fmaxf(v[1], v[2]));
        #pragma unroll
        for (int o = 16; o > 0; o >>= 1)
            mx = fmaxf(mx, __shfl_xor_sync(0xffffffffu, mx, o));
        float e[3];
        float ssum = 0.0f;
        #pragma unroll
        for (int i = 0; i < 3; i++) {
            int r = lane + 32 * i;
            e[i] = (r < len) ? __expf(v[i] - mx) : 0.0f;
            ssum += e[i];
        }
        #pragma unroll
        for (int o = 16; o > 0; o >>= 1)
            ssum += __shfl_xor_sync(0xffffffffu, ssum, o);
        float inv = 1.0f / ssum;
        #pragma unroll
        for (int i = 0; i < 3; i++) {
            int r = lane + 32 * i;
            attn_s[r] = (r < len) ? e[i] * inv : 0.0f;
        }
    }
    __syncthreads();

    // fused out GEMV from fp16 x: out[b,:] = sum_s attn_s[s] * xh[b,start+s,:]
    {
        const uint2* xb = reinterpret_cast<const uint2*>(
            g_xh + (size_t)(b * Sn + start) * En);
        float4 a0 = make_float4(0.f, 0.f, 0.f, 0.f);
        float4 a1 = make_float4(0.f, 0.f, 0.f, 0.f);
        int s = 0;
        for (; s + 2 <= len; s += 2) {
            float w0 = attn_s[s], w1 = attn_s[s + 1];
            uint2 v0 = xb[(size_t)s * (En / 4) + tid];
            uint2 v1 = xb[(size_t)(s + 1) * (En / 4) + tid];
            float2 p0 = __half22float2(*reinterpret_cast<__half2*>(&v0.x));
            float2 p1 = __half22float2(*reinterpret_cast<__half2*>(&v0.y));
            float2 q0 = __half22float2(*reinterpret_cast<__half2*>(&v1.x));
            float2 q1 = __half22float2(*reinterpret_cast<__half2*>(&v1.y));
            a0.x += w0 * p0.x; a0.y += w0 * p0.y; a0.z += w0 * p1.x; a0.w += w0 * p1.y;
            a1.x += w1 * q0.x; a1.y += w1 * q0.y; a1.z += w1 * q1.x; a1.w += w1 * q1.y;
        }
        if (s < len) {
            float w0 = attn_s[s];
            uint2 v0 = xb[(size_t)s * (En / 4) + tid];
            float2 p0 = __half22float2(*reinterpret_cast<__half2*>(&v0.x));
            float2 p1 = __half22float2(*reinterpret_cast<__half2*>(&v0.y));
            a0.x += w0 * p0.x; a0.y += w0 * p0.y; a0.z += w0 * p1.x; a0.w += w0 * p1.y;
        }
        a0.x += a1.x; a0.y += a1.y; a0.z += a1.z; a0.w += a1.w;
        reinterpret_cast<float4*>(out)[(size_t)b * (En / 4) + tid] = a0;
    }

    // fused keep_attention (last batch only): zeros outside the bag
    if (b == Bn - 1 && tid < Sn) {
        int r = tid - start;
        out[(size_t)Bn * En + tid] = (r >= 0 && r < len) ? attn_s[r] : 0.0f;
    }
}

// ---------------------------------------------------------------------------
extern "C" void kernel_launch(void* const* d_in, const int* in_sizes, int n_in,
                              void* d_out, int out_size) {
    const float* x   = (const float*)d_in[0];
    const float* W   = (const float*)d_in[1];
    const float* u   = (const float*)d_in[2];
    const int*   doc = (const int*)d_in[3];
    float* out = (float*)d_out;

    conv_kernel<<<1024 + Bn, 256>>>((const float4*)W, (const float4*)x, doc);

    cudaFuncSetAttribute(scores_kernel,
                         cudaFuncAttributeMaxDynamicSharedMemorySize, SMEM_TOTAL);
    scores_kernel<<<Bn, NTHR, SMEM_TOTAL>>>(u, doc, out);
}

// round 10
// speedup vs baseline: 1.3300x; 1.1597x over previous
#include <cuda_runtime.h>
#include <cuda_fp16.h>
#include <cstdint>
#include <cstddef>

#define Bn 256
#define Sn 128
#define En 1024

constexpr int MT   = 64;            // 4 subtiles of 16 rows per CTA
constexpr int NT   = 128;           // f-columns per chunk
constexpr int KT   = 128;           // K halfs per tile (256B rows)
constexpr int NFC  = En / NT;       // 8
constexpr int NKT  = En / KT;       // 8
constexpr int TILES = NFC * NKT;    // 64
constexpr int NTHR = 256;           // 8 warps: 2 (M) x 4 (N)
constexpr int WMN  = 2;
constexpr int WNN  = 4;

constexpr int A_TILE_B = MT * KT * 2;   // 16384
constexpr int B_TILE_B = NT * KT * 2;   // 32768
constexpr int STG_B    = A_TILE_B + B_TILE_B;     // 49152
constexpr int OFF_ITEM = 2 * STG_B;               // 98304
constexpr int SMEM_TOTAL = OFF_ITEM + 32;         // 98336 -> 2 CTAs/SM
constexpr int OFF_SP   = 0;          // s_part aliases stage 0 (post-loop only;
                                     // last tile 63 is odd -> reads stage 1)

constexpr int GEMM_GRID = 384;       // covers worst-case T=1536
constexpr int LIVE      = 296;       // 2 x 148 SMs: uniform single wave
constexpr int MAX_ITEMS = 1536;

// device-global scratch (allocations are forbidden)
__device__ __half g_Wh[En * En];
__device__ __half g_xh[Bn * Sn * En];
__device__ float  g_scp[GEMM_GRID * MT];    // per-item-row scores
__device__ int    g_itembase[Bn + 1];
__device__ int    g_item_src[MAX_ITEMS];    // b*Sn + start + st*16
__device__ int    g_item_val[MAX_ITEMS];    // valid rows in subtile (0..16)

// ---------------------------------------------------------------------------
__device__ __forceinline__ void cp16(uint32_t dst, const void* src, bool pred) {
    int sz = pred ? 16 : 0;
    asm volatile("cp.async.cg.shared.global [%0], [%1], 16, %2;\n"
                 :: "r"(dst), "l"(src), "r"(sz));
}
__device__ __forceinline__ void cp_commit() {
    asm volatile("cp.async.commit_group;\n");
}
__device__ __forceinline__ void cp_wait0() {
    asm volatile("cp.async.wait_group 0;\n");
}

__device__ __forceinline__ float tanha(float x) {
    float y;
    asm("tanh.approx.f32 %0, %1;" : "=f"(y) : "f"(x));
    return y;
}

__device__ __forceinline__ void ldsm4(uint32_t& r0, uint32_t& r1,
                                      uint32_t& r2, uint32_t& r3, uint32_t addr) {
    asm volatile("ldmatrix.sync.aligned.m8n8.x4.shared.b16 {%0,%1,%2,%3}, [%4];"
                 : "=r"(r0), "=r"(r1), "=r"(r2), "=r"(r3) : "r"(addr));
}

__device__ __forceinline__ void mma16816(float* c,
                                         uint32_t a0, uint32_t a1, uint32_t a2, uint32_t a3,
                                         uint32_t b0, uint32_t b1) {
    asm volatile(
        "mma.sync.aligned.m16n8k16.row.col.f32.f16.f16.f32 "
        "{%0,%1,%2,%3},{%4,%5,%6,%7},{%8,%9},{%0,%1,%2,%3};"
        : "+f"(c[0]), "+f"(c[1]), "+f"(c[2]), "+f"(c[3])
        : "r"(a0), "r"(a1), "r"(a2), "r"(a3), "r"(b0), "r"(b1));
}

// ---------------------------------------------------------------------------
// conv + setup kernel: blocks [0,1024) convert W, [1024,1280) convert x,
// block 1280 builds the subtile work list (deterministic serial prefix).
// ---------------------------------------------------------------------------
__global__ __launch_bounds__(256)
void conv_kernel(const float4* __restrict__ W4,
                 const float4* __restrict__ x4,
                 const int* __restrict__ doc) {
    const int bx = blockIdx.x;
    const int t  = threadIdx.x;
    if (bx < 1024) {
        int idx = bx * 256 + t;
        float4 v = W4[idx];
        __half2* o = reinterpret_cast<__half2*>(g_Wh);
        o[idx * 2]     = __floats2half2_rn(v.x, v.y);
        o[idx * 2 + 1] = __floats2half2_rn(v.z, v.w);
    } else if (bx < 1024 + Bn) {
        const int b = bx - 1024;
        const int start = doc[2 * b];
        const int end   = doc[2 * b + 1];
        __half2* o = reinterpret_cast<__half2*>(g_xh);
        for (int s = start; s < end; s++) {
            size_t base = (size_t)(b * Sn + s) * (En / 4) + t;
            float4 v = x4[base];
            o[base * 2]     = __floats2half2_rn(v.x, v.y);
            o[base * 2 + 1] = __floats2half2_rn(v.z, v.w);
        }
    } else {
        // setup block: 256 threads, one per bag
        __shared__ int nmt_s[Bn];
        const int b = t;
        const int start = doc[2 * b];
        const int len   = doc[2 * b + 1] - start;
        const int nmt   = (len + 15) >> 4;
        nmt_s[b] = nmt;
        __syncthreads();
        if (t == 0) {
            int acc = 0;
            for (int i = 0; i < Bn; i++) { g_itembase[i] = acc; acc += nmt_s[i]; }
            g_itembase[Bn] = acc;   // T
        }
        __syncthreads();
        const int base = g_itembase[b];
        for (int st = 0; st < nmt; st++) {
            int v = len - st * 16; if (v > 16) v = 16;
            g_item_src[base + st] = b * Sn + start + st * 16;
            g_item_val[base + st] = v;
        }
        __syncthreads();
        const int T = g_itembase[Bn];
        for (int i = T + t; i < MAX_ITEMS; i += 256) {
            g_item_src[i] = 0;
            g_item_val[i] = 0;
        }
    }
}

// ---------------------------------------------------------------------------
// GEMM kernel: uniform 4-subtile M tiles (work-list), full-E sweep, writes
// per-row score partial sums to g_scp. Perfectly balanced: 296 equal CTAs.
// ---------------------------------------------------------------------------
extern __shared__ char smem[];

__global__ __launch_bounds__(NTHR, 2)
void gemm_kernel(const float* __restrict__ u) {
    const int grp = blockIdx.x;
    if (grp >= LIVE && grp * 4 >= g_itembase[Bn]) return;   // overflow guard

    const int tid  = threadIdx.x;
    const int lane = tid & 31;
    const int wid  = tid >> 5;
    const int wm   = wid % WMN;       // subtiles wm*2, wm*2+1
    const int wn   = wid / WMN;       // cols [wn*32, wn*32+32)
    const int g    = lane >> 2;
    const int tg   = lane & 3;

    const uint32_t smem_u32 = (uint32_t)__cvta_generic_to_shared(smem);
    float* s_part = reinterpret_cast<float*>(smem + OFF_SP);
    int*   item_s = reinterpret_cast<int*>(smem + OFF_ITEM);

    if (tid < 4) {
        item_s[tid]     = g_item_src[grp * 4 + tid];
        item_s[4 + tid] = g_item_val[grp * 4 + tid];
    }
    __syncthreads();

    const int fa_m = tid >> 4;        // 0..15 row within 16-row band
    const int fa_c = tid & 15;        // 16B chunk in 256B row
    const int swz  = (fa_c ^ (fa_m & 7)) << 4;   // m&7 == fa_m&7 for all bands

    const __half* arow[4];
    bool apred[4];
    #pragma unroll
    for (int i = 0; i < 4; i++) {
        arow[i]  = g_xh + (size_t)(item_s[i] + fa_m) * En + fa_c * 8;
        apred[i] = fa_m < item_s[4 + i];
    }

    auto fill_full = [&](int t) {
        const int fc = t >> 3;
        const int k0 = (t & 7) * KT;
        const uint32_t aBase = smem_u32 + (t & 1) * STG_B;
        const uint32_t bBase = aBase + A_TILE_B;
        #pragma unroll
        for (int i = 0; i < 4; i++) {
            int m = fa_m + i * 16;
            cp16(aBase + m * 256 + swz, arow[i] + k0, apred[i]);
        }
        #pragma unroll
        for (int i = 0; i < 8; i++) {
            int n = fa_m + i * 16;
            cp16(bBase + n * 256 + swz,
                 g_Wh + (size_t)(fc * NT + n) * En + k0 + fa_c * 8, true);
        }
        cp_commit();
    };

    float acc[2][4][4];
    #pragma unroll
    for (int ms = 0; ms < 2; ms++)
        #pragma unroll
        for (int j = 0; j < 4; j++)
            #pragma unroll
            for (int i = 0; i < 4; i++) acc[ms][j][i] = 0.0f;
    float sacc[2][2] = {{0.f,0.f},{0.f,0.f}};

    const int a_row   = (lane & 15);
    const int a_choff = (lane >> 4);
    const int b_rowin = (lane & 7) + ((lane >> 4) << 3);
    const int b_choff = ((lane >> 3) & 1);

    fill_full(0);

    for (int fc = 0; fc < NFC; fc++) {
        for (int k = 0; k < NKT; k++) {
            const int t = fc * NKT + k;
            cp_wait0();
            __syncthreads();

            const uint32_t aBase = smem_u32 + (t & 1) * STG_B;
            const uint32_t bBase = aBase + A_TILE_B;

            const bool have_next = (t + 1 < TILES);
            const int  nfc = (t + 1) >> 3;
            const int  nk0 = ((t + 1) & 7) * KT;
            const uint32_t naBase = smem_u32 + ((t + 1) & 1) * STG_B;
            const uint32_t nbBase = naBase + A_TILE_B;

            #pragma unroll
            for (int ks = 0; ks < 8; ks++) {
                // interleaved fills of tile t+1 (~1.5 cp.async per ks)
                if (have_next) {
                    if (ks < 4) {
                        int m = fa_m + ks * 16;
                        cp16(naBase + m * 256 + swz, arow[ks] + nk0, apred[ks]);
                    }
                    {
                        int n = fa_m + ks * 16;
                        cp16(nbBase + n * 256 + swz,
                             g_Wh + (size_t)(nfc * NT + n) * En + nk0 + fa_c * 8, true);
                    }
                }

                // compute
                uint32_t af[2][4];
                #pragma unroll
                for (int ms = 0; ms < 2; ms++) {
                    int row = (wm * 2 + ms) * 16 + a_row;
                    int chv = 2 * ks + a_choff;
                    uint32_t addr = aBase + row * 256 + ((chv ^ (row & 7)) << 4);
                    ldsm4(af[ms][0], af[ms][1], af[ms][2], af[ms][3], addr);
                }
                uint32_t bf[2][4];
                #pragma unroll
                for (int jp = 0; jp < 2; jp++) {
                    int nrow = wn * 32 + jp * 16 + b_rowin;
                    int chv = 2 * ks + b_choff;
                    uint32_t addr = bBase + nrow * 256 + ((chv ^ (nrow & 7)) << 4);
                    ldsm4(bf[jp][0], bf[jp][1], bf[jp][2], bf[jp][3], addr);
                }
                #pragma unroll
                for (int ms = 0; ms < 2; ms++) {
                    #pragma unroll
                    for (int j = 0; j < 4; j++) {
                        mma16816(acc[ms][j],
                                 af[ms][0], af[ms][1], af[ms][2], af[ms][3],
                                 bf[j >> 1][(j & 1) * 2], bf[j >> 1][(j & 1) * 2 + 1]);
                    }
                }
            }
            cp_commit();
        }

        // f-chunk epilogue: scores += tanh(z) * u   (u via __ldg, L1-hot)
        #pragma unroll
        for (int ms = 0; ms < 2; ms++) {
            #pragma unroll
            for (int j = 0; j < 4; j++) {
                int f = fc * NT + wn * 32 + j * 8 + 2 * tg;
                float u0 = __ldg(u + f), u1 = __ldg(u + f + 1);
                sacc[ms][0] += tanha(acc[ms][j][0]) * u0 + tanha(acc[ms][j][1]) * u1;
                sacc[ms][1] += tanha(acc[ms][j][2]) * u0 + tanha(acc[ms][j][3]) * u1;
                acc[ms][j][0] = 0.f; acc[ms][j][1] = 0.f;
                acc[ms][j][2] = 0.f; acc[ms][j][3] = 0.f;
            }
        }
    }

    // deterministic tg-reduction -> s_part (aliases stage 0; last tile read stage 1)
    #pragma unroll
    for (int ms = 0; ms < 2; ms++) {
        #pragma unroll
        for (int rg = 0; rg < 2; rg++) {
            float v = sacc[ms][rg];
            v += __shfl_xor_sync(0xffffffffu, v, 1);
            v += __shfl_xor_sync(0xffffffffu, v, 2);
            if (tg == 0) {
                int row = (wm * 2 + ms) * 16 + rg * 8 + g;
                s_part[row * WNN + wn] = v;
            }
        }
    }
    __syncthreads();

    // warp 0 sums the 4 N-partials per row and writes global scores
    if (wid == 0) {
        #pragma unroll
        for (int i = 0; i < 2; i++) {
            int r = lane + 32 * i;
            float sv = s_part[r * WNN + 0] + s_part[r * WNN + 1] +
                       s_part[r * WNN + 2] + s_part[r * WNN + 3];
            g_scp[grp * MT + r] = sv;
        }
    }
}

// ---------------------------------------------------------------------------
// Finish kernel: per-bag softmax + fp16 GEMV + keep_attention.
// ---------------------------------------------------------------------------
__global__ __launch_bounds__(256)
void finish_kernel(const int* __restrict__ doc, float* __restrict__ out) {
    const int b    = blockIdx.x;
    const int tid  = threadIdx.x;
    const int lane = tid & 31;
    const int wid  = tid >> 5;

    __shared__ float attn_s[96];

    const int start = doc[2 * b];
    const int len   = doc[2 * b + 1] - start;    // 1..96
    const int ib    = g_itembase[b];

    if (wid == 0) {
        float v[3];
        #pragma unroll
        for (int i = 0; i < 3; i++) {
            int r = lane + 32 * i;
            v[i] = (r < len)
                 ? g_scp[(ib + (r >> 4)) * 16 + (r & 15)]
                 : -3.0e38f;
        }
        float mx = fmaxf(v[0], fmaxf(v[1], v[2]));
        #pragma unroll
        for (int o = 16; o > 0; o >>= 1)
            mx = fmaxf(mx, __shfl_xor_sync(0xffffffffu, mx, o));
        float e[3];
        float ssum = 0.0f;
        #pragma unroll
        for (int i = 0; i < 3; i++) {
            int r = lane + 32 * i;
            e[i] = (r < len) ? __expf(v[i] - mx) : 0.0f;
            ssum += e[i];
        }
        #pragma unroll
        for (int o = 16; o > 0; o >>= 1)
            ssum += __shfl_xor_sync(0xffffffffu, ssum, o);
        float inv = 1.0f / ssum;
        #pragma unroll
        for (int i = 0; i < 3; i++) {
            int r = lane + 32 * i;
            attn_s[r] = (r < len) ? e[i] * inv : 0.0f;
        }
    }
    __syncthreads();

    // out GEMV from fp16 x
    {
        const uint2* xb = reinterpret_cast<const uint2*>(
            g_xh + (size_t)(b * Sn + start) * En);
        float4 a0 = make_float4(0.f, 0.f, 0.f, 0.f);
        float4 a1 = make_float4(0.f, 0.f, 0.f, 0.f);
        int s = 0;
        for (; s + 2 <= len; s += 2) {
            float w0 = attn_s[s], w1 = attn_s[s + 1];
            uint2 v0 = xb[(size_t)s * (En / 4) + tid];
            uint2 v1 = xb[(size_t)(s + 1) * (En / 4) + tid];
            float2 p0 = __half22float2(*reinterpret_cast<__half2*>(&v0.x));
            float2 p1 = __half22float2(*reinterpret_cast<__half2*>(&v0.y));
            float2 q0 = __half22float2(*reinterpret_cast<__half2*>(&v1.x));
            float2 q1 = __half22float2(*reinterpret_cast<__half2*>(&v1.y));
            a0.x += w0 * p0.x; a0.y += w0 * p0.y; a0.z += w0 * p1.x; a0.w += w0 * p1.y;
            a1.x += w1 * q0.x; a1.y += w1 * q0.y; a1.z += w1 * q1.x; a1.w += w1 * q1.y;
        }
        if (s < len) {
            float w0 = attn_s[s];
            uint2 v0 = xb[(size_t)s * (En / 4) + tid];
            float2 p0 = __half22float2(*reinterpret_cast<__half2*>(&v0.x));
            float2 p1 = __half22float2(*reinterpret_cast<__half2*>(&v0.y));
            a0.x += w0 * p0.x; a0.y += w0 * p0.y; a0.z += w0 * p1.x; a0.w += w0 * p1.y;
        }
        a0.x += a1.x; a0.y += a1.y; a0.z += a1.z; a0.w += a1.w;
        reinterpret_cast<float4*>(out)[(size_t)b * (En / 4) + tid] = a0;
    }

    // keep_attention (last batch only): zeros outside the bag
    if (b == Bn - 1 && tid < Sn) {
        int r = tid - start;
        out[(size_t)Bn * En + tid] = (r >= 0 && r < len) ? attn_s[r] : 0.0f;
    }
}

// ---------------------------------------------------------------------------
extern "C" void kernel_launch(void* const* d_in, const int* in_sizes, int n_in,
                              void* d_out, int out_size) {
    const float* x   = (const float*)d_in[0];
    const float* W   = (const float*)d_in[1];
    const float* u   = (const float*)d_in[2];
    const int*   doc = (const int*)d_in[3];
    float* out = (float*)d_out;

    conv_kernel<<<1024 + Bn + 1, 256>>>((const float4*)W, (const float4*)x, doc);

    cudaFuncSetAttribute(gemm_kernel,
                         cudaFuncAttributeMaxDynamicSharedMemorySize, SMEM_TOTAL);
    gemm_kernel<<<GEMM_GRID, NTHR, SMEM_TOTAL>>>(u);

    finish_kernel<<<Bn, 256>>>(doc, out);
}

// round 11
// speedup vs baseline: 1.4257x; 1.0719x over previous
#include <cuda_runtime.h>
#include <cuda_fp16.h>
#include <cstdint>
#include <cstddef>

#define Bn 256
#define Sn 128
#define En 1024

constexpr int MT   = 64;            // 4 subtiles of 16 rows per CTA
constexpr int NT   = 128;           // f-columns per chunk
constexpr int KT   = 128;           // K halfs per tile (256B rows)
constexpr int NFC  = En / NT;       // 8
constexpr int NKT  = En / KT;       // 8
constexpr int TILES = NFC * NKT;    // 64
constexpr int NTHR = 256;           // 8 warps: 2 (M) x 4 (N)
constexpr int WMN  = 2;
constexpr int WNN  = 4;

constexpr int A_TILE_B = MT * KT * 2;   // 16384
constexpr int B_TILE_B = NT * KT * 2;   // 32768
constexpr int STG_B    = A_TILE_B + B_TILE_B;     // 49152
constexpr int OFF_ITEM = 2 * STG_B;               // 98304
constexpr int SMEM_TOTAL = OFF_ITEM + 32;         // 98336 -> 2 CTAs/SM
constexpr int OFF_SP   = 0;          // s_part aliases stage 0 (post-loop only;
                                     // last tile 63 is odd -> reads stage 1)

constexpr int GEMM_GRID = 384;       // covers worst-case T=1536
constexpr int LIVE      = 296;       // 2 x 148 SMs: uniform single wave
constexpr int MAX_ITEMS = 1536;

constexpr int XBLK  = 24;            // x-convert blocks per bag (4 rows each)

// device-global scratch (allocations are forbidden)
__device__ __half g_Wh[En * En];
__device__ __half g_xh[Bn * Sn * En];
__device__ float  g_scp[GEMM_GRID * MT];    // per-item-row scores
__device__ int    g_itembase[Bn + 1];
__device__ int    g_item_src[MAX_ITEMS];    // b*Sn + start + st*16
__device__ int    g_item_val[MAX_ITEMS];    // valid rows in subtile (0..16)

// ---------------------------------------------------------------------------
__device__ __forceinline__ void cp16(uint32_t dst, const void* src, bool pred) {
    int sz = pred ? 16 : 0;
    asm volatile("cp.async.cg.shared.global [%0], [%1], 16, %2;\n"
                 :: "r"(dst), "l"(src), "r"(sz));
}
__device__ __forceinline__ void cp_commit() {
    asm volatile("cp.async.commit_group;\n");
}
__device__ __forceinline__ void cp_wait0() {
    asm volatile("cp.async.wait_group 0;\n");
}

__device__ __forceinline__ float tanha(float x) {
    float y;
    asm("tanh.approx.f32 %0, %1;" : "=f"(y) : "f"(x));
    return y;
}

__device__ __forceinline__ void ldsm4(uint32_t& r0, uint32_t& r1,
                                      uint32_t& r2, uint32_t& r3, uint32_t addr) {
    asm volatile("ldmatrix.sync.aligned.m8n8.x4.shared.b16 {%0,%1,%2,%3}, [%4];"
                 : "=r"(r0), "=r"(r1), "=r"(r2), "=r"(r3) : "r"(addr));
}

__device__ __forceinline__ void mma16816(float* c,
                                         uint32_t a0, uint32_t a1, uint32_t a2, uint32_t a3,
                                         uint32_t b0, uint32_t b1) {
    asm volatile(
        "mma.sync.aligned.m16n8k16.row.col.f32.f16.f16.f32 "
        "{%0,%1,%2,%3},{%4,%5,%6,%7},{%8,%9},{%0,%1,%2,%3};"
        : "+f"(c[0]), "+f"(c[1]), "+f"(c[2]), "+f"(c[3])
        : "r"(a0), "r"(a1), "r"(a2), "r"(a3), "r"(b0), "r"(b1));
}

// ---------------------------------------------------------------------------
// conv + setup kernel:
//   blocks [0, 1024)                 : convert W (fp32 -> fp16)
//   blocks [1024, 1024 + Bn*XBLK)    : convert x bag rows, 4 rows/block, MLP=4
//   block  1024 + Bn*XBLK            : build subtile work list
// ---------------------------------------------------------------------------
__global__ __launch_bounds__(256)
void conv_kernel(const float4* __restrict__ W4,
                 const float4* __restrict__ x4,
                 const int* __restrict__ doc) {
    const int bx = blockIdx.x;
    const int t  = threadIdx.x;
    if (bx < 1024) {
        int idx = bx * 256 + t;
        float4 v = W4[idx];
        __half2* o = reinterpret_cast<__half2*>(g_Wh);
        o[idx * 2]     = __floats2half2_rn(v.x, v.y);
        o[idx * 2 + 1] = __floats2half2_rn(v.z, v.w);
    } else if (bx < 1024 + Bn * XBLK) {
        const int b  = (bx - 1024) / XBLK;
        const int gq = (bx - 1024) % XBLK;      // row group: 4 rows
        const int start = doc[2 * b];
        const int end   = doc[2 * b + 1];
        __half2* o = reinterpret_cast<__half2*>(g_xh);
        #pragma unroll
        for (int i = 0; i < 4; i++) {
            int s = start + gq * 4 + i;
            if (s < end) {
                size_t base = (size_t)(b * Sn + s) * (En / 4) + t;
                float4 v = x4[base];
                o[base * 2]     = __floats2half2_rn(v.x, v.y);
                o[base * 2 + 1] = __floats2half2_rn(v.z, v.w);
            }
        }
    } else {
        // setup block: 256 threads, one per bag
        __shared__ int nmt_s[Bn];
        const int b = t;
        const int start = doc[2 * b];
        const int len   = doc[2 * b + 1] - start;
        const int nmt   = (len + 15) >> 4;
        nmt_s[b] = nmt;
        __syncthreads();
        if (t == 0) {
            int acc = 0;
            for (int i = 0; i < Bn; i++) { g_itembase[i] = acc; acc += nmt_s[i]; }
            g_itembase[Bn] = acc;   // T
        }
        __syncthreads();
        const int base = g_itembase[b];
        for (int st = 0; st < nmt; st++) {
            int v = len - st * 16; if (v > 16) v = 16;
            g_item_src[base + st] = b * Sn + start + st * 16;
            g_item_val[base + st] = v;
        }
        __syncthreads();
        const int T = g_itembase[Bn];
        for (int i = T + t; i < MAX_ITEMS; i += 256) {
            g_item_src[i] = 0;
            g_item_val[i] = 0;
        }
    }
}

// ---------------------------------------------------------------------------
// GEMM kernel: uniform 4-subtile M tiles (work-list), full-E sweep, writes
// per-item-row score partial sums to g_scp. 296 equal CTAs, single wave.
// ---------------------------------------------------------------------------
extern __shared__ char smem[];

__global__ __launch_bounds__(NTHR, 2)
void gemm_kernel(const float* __restrict__ u) {
    const int grp = blockIdx.x;
    if (grp >= LIVE && grp * 4 >= g_itembase[Bn]) return;   // overflow guard

    const int tid  = threadIdx.x;
    const int lane = tid & 31;
    const int wid  = tid >> 5;
    const int wm   = wid % WMN;       // subtiles wm*2, wm*2+1
    const int wn   = wid / WMN;       // cols [wn*32, wn*32+32)
    const int g    = lane >> 2;
    const int tg   = lane & 3;

    const uint32_t smem_u32 = (uint32_t)__cvta_generic_to_shared(smem);
    float* s_part = reinterpret_cast<float*>(smem + OFF_SP);
    int*   item_s = reinterpret_cast<int*>(smem + OFF_ITEM);

    if (tid < 4) {
        item_s[tid]     = g_item_src[grp * 4 + tid];
        item_s[4 + tid] = g_item_val[grp * 4 + tid];
    }
    __syncthreads();

    const int fa_m = tid >> 4;        // 0..15 row within 16-row band
    const int fa_c = tid & 15;        // 16B chunk in 256B row
    const int swz  = (fa_c ^ (fa_m & 7)) << 4;   // m&7 == fa_m&7 for all bands

    const __half* arow[4];
    bool apred[4];
    #pragma unroll
    for (int i = 0; i < 4; i++) {
        arow[i]  = g_xh + (size_t)(item_s[i] + fa_m) * En + fa_c * 8;
        apred[i] = fa_m < item_s[4 + i];
    }

    auto fill_full = [&](int t) {
        const int fc = t >> 3;
        const int k0 = (t & 7) * KT;
        const uint32_t aBase = smem_u32 + (t & 1) * STG_B;
        const uint32_t bBase = aBase + A_TILE_B;
        #pragma unroll
        for (int i = 0; i < 4; i++) {
            int m = fa_m + i * 16;
            cp16(aBase + m * 256 + swz, arow[i] + k0, apred[i]);
        }
        #pragma unroll
        for (int i = 0; i < 8; i++) {
            int n = fa_m + i * 16;
            cp16(bBase + n * 256 + swz,
                 g_Wh + (size_t)(fc * NT + n) * En + k0 + fa_c * 8, true);
        }
        cp_commit();
    };

    float acc[2][4][4];
    #pragma unroll
    for (int ms = 0; ms < 2; ms++)
        #pragma unroll
        for (int j = 0; j < 4; j++)
            #pragma unroll
            for (int i = 0; i < 4; i++) acc[ms][j][i] = 0.0f;
    float sacc[2][2] = {{0.f,0.f},{0.f,0.f}};

    const int a_row   = (lane & 15);
    const int a_choff = (lane >> 4);
    const int b_rowin = (lane & 7) + ((lane >> 4) << 3);
    const int b_choff = ((lane >> 3) & 1);

    fill_full(0);

    for (int fc = 0; fc < NFC; fc++) {
        for (int k = 0; k < NKT; k++) {
            const int t = fc * NKT + k;
            cp_wait0();
            __syncthreads();

            const uint32_t aBase = smem_u32 + (t & 1) * STG_B;
            const uint32_t bBase = aBase + A_TILE_B;

            const bool have_next = (t + 1 < TILES);
            const int  nfc = (t + 1) >> 3;
            const int  nk0 = ((t + 1) & 7) * KT;
            const uint32_t naBase = smem_u32 + ((t + 1) & 1) * STG_B;
            const uint32_t nbBase = naBase + A_TILE_B;

            #pragma unroll
            for (int ks = 0; ks < 8; ks++) {
                // interleaved fills of tile t+1 (~1.5 cp.async per ks)
                if (have_next) {
                    if (ks < 4) {
                        int m = fa_m + ks * 16;
                        cp16(naBase + m * 256 + swz, arow[ks] + nk0, apred[ks]);
                    }
                    {
                        int n = fa_m + ks * 16;
                        cp16(nbBase + n * 256 + swz,
                             g_Wh + (size_t)(nfc * NT + n) * En + nk0 + fa_c * 8, true);
                    }
                }

                // compute
                uint32_t af[2][4];
                #pragma unroll
                for (int ms = 0; ms < 2; ms++) {
                    int row = (wm * 2 + ms) * 16 + a_row;
                    int chv = 2 * ks + a_choff;
                    uint32_t addr = aBase + row * 256 + ((chv ^ (row & 7)) << 4);
                    ldsm4(af[ms][0], af[ms][1], af[ms][2], af[ms][3], addr);
                }
                uint32_t bf[2][4];
                #pragma unroll
                for (int jp = 0; jp < 2; jp++) {
                    int nrow = wn * 32 + jp * 16 + b_rowin;
                    int chv = 2 * ks + b_choff;
                    uint32_t addr = bBase + nrow * 256 + ((chv ^ (nrow & 7)) << 4);
                    ldsm4(bf[jp][0], bf[jp][1], bf[jp][2], bf[jp][3], addr);
                }
                #pragma unroll
                for (int ms = 0; ms < 2; ms++) {
                    #pragma unroll
                    for (int j = 0; j < 4; j++) {
                        mma16816(acc[ms][j],
                                 af[ms][0], af[ms][1], af[ms][2], af[ms][3],
                                 bf[j >> 1][(j & 1) * 2], bf[j >> 1][(j & 1) * 2 + 1]);
                    }
                }
            }
            cp_commit();
        }

        // f-chunk epilogue: scores += tanh(z) * u   (u via __ldg, L1-hot)
        #pragma unroll
        for (int ms = 0; ms < 2; ms++) {
            #pragma unroll
            for (int j = 0; j < 4; j++) {
                int f = fc * NT + wn * 32 + j * 8 + 2 * tg;
                float u0 = __ldg(u + f), u1 = __ldg(u + f + 1);
                sacc[ms][0] += tanha(acc[ms][j][0]) * u0 + tanha(acc[ms][j][1]) * u1;
                sacc[ms][1] += tanha(acc[ms][j][2]) * u0 + tanha(acc[ms][j][3]) * u1;
                acc[ms][j][0] = 0.f; acc[ms][j][1] = 0.f;
                acc[ms][j][2] = 0.f; acc[ms][j][3] = 0.f;
            }
        }
    }

    // deterministic tg-reduction -> s_part (aliases stage 0; last tile read stage 1)
    #pragma unroll
    for (int ms = 0; ms < 2; ms++) {
        #pragma unroll
        for (int rg = 0; rg < 2; rg++) {
            float v = sacc[ms][rg];
            v += __shfl_xor_sync(0xffffffffu, v, 1);
            v += __shfl_xor_sync(0xffffffffu, v, 2);
            if (tg == 0) {
                int row = (wm * 2 + ms) * 16 + rg * 8 + g;
                s_part[row * WNN + wn] = v;
            }
        }
    }
    __syncthreads();

    // warp 0 sums the 4 N-partials per row and writes global scores
    if (wid == 0) {
        #pragma unroll
        for (int i = 0; i < 2; i++) {
            int r = lane + 32 * i;
            float sv = s_part[r * WNN + 0] + s_part[r * WNN + 1] +
                       s_part[r * WNN + 2] + s_part[r * WNN + 3];
            g_scp[grp * MT + r] = sv;
        }
    }
}

// ---------------------------------------------------------------------------
// Finish kernel: per-bag softmax + fp16 GEMV (unroll x4) + keep_attention.
// ---------------------------------------------------------------------------
__global__ __launch_bounds__(256)
void finish_kernel(const int* __restrict__ doc, float* __restrict__ out) {
    const int b    = blockIdx.x;
    const int tid  = threadIdx.x;
    const int lane = tid & 31;
    const int wid  = tid >> 5;

    __shared__ float attn_s[96];

    const int start = doc[2 * b];
    const int len   = doc[2 * b + 1] - start;    // 1..96
    const int ib    = g_itembase[b];

    if (wid == 0) {
        float v[3];
        #pragma unroll
        for (int i = 0; i < 3; i++) {
            int r = lane + 32 * i;
            v[i] = (r < len)
                 ? g_scp[(ib + (r >> 4)) * 16 + (r & 15)]
                 : -3.0e38f;
        }
        float mx = fmaxf(v[0], fmaxf(v[1], v[2]));
        #pragma unroll
        for (int o = 16; o > 0; o >>= 1)
            mx = fmaxf(mx, __shfl_xor_sync(0xffffffffu, mx, o));
        float e[3];
        float ssum = 0.0f;
        #pragma unroll
        for (int i = 0; i < 3; i++) {
            int r = lane + 32 * i;
            e[i] = (r < len) ? __expf(v[i] - mx) : 0.0f;
            ssum += e[i];
        }
        #pragma unroll
        for (int o = 16; o > 0; o >>= 1)
            ssum += __shfl_xor_sync(0xffffffffu, ssum, o);
        float inv = 1.0f / ssum;
        #pragma unroll
        for (int i = 0; i < 3; i++) {
            int r = lane + 32 * i;
            attn_s[r] = (r < len) ? e[i] * inv : 0.0f;
        }
    }
    __syncthreads();

    // out GEMV from fp16 x, 4-way unrolled for MLP
    {
        const uint2* xb = reinterpret_cast<const uint2*>(
            g_xh + (size_t)(b * Sn + start) * En);
        float4 a0 = make_float4(0.f, 0.f, 0.f, 0.f);
        float4 a1 = make_float4(0.f, 0.f, 0.f, 0.f);
        float4 a2 = make_float4(0.f, 0.f, 0.f, 0.f);
        float4 a3 = make_float4(0.f, 0.f, 0.f, 0.f);
        int s = 0;
        for (; s + 4 <= len; s += 4) {
            float w0 = attn_s[s],     w1 = attn_s[s + 1];
            float w2 = attn_s[s + 2], w3 = attn_s[s + 3];
            uint2 v0 = xb[(size_t)s * (En / 4) + tid];
            uint2 v1 = xb[(size_t)(s + 1) * (En / 4) + tid];
            uint2 v2 = xb[(size_t)(s + 2) * (En / 4) + tid];
            uint2 v3 = xb[(size_t)(s + 3) * (En / 4) + tid];
            float2 p0 = __half22float2(*reinterpret_cast<__half2*>(&v0.x));
            float2 p1 = __half22float2(*reinterpret_cast<__half2*>(&v0.y));
            float2 q0 = __half22float2(*reinterpret_cast<__half2*>(&v1.x));
            float2 q1 = __half22float2(*reinterpret_cast<__half2*>(&v1.y));
            float2 r0 = __half22float2(*reinterpret_cast<__half2*>(&v2.x));
            float2 r1 = __half22float2(*reinterpret_cast<__half2*>(&v2.y));
            float2 s0 = __half22float2(*reinterpret_cast<__half2*>(&v3.x));
            float2 s1 = __half22float2(*reinterpret_cast<__half2*>(&v3.y));
            a0.x += w0 * p0.x; a0.y += w0 * p0.y; a0.z += w0 * p1.x; a0.w += w0 * p1.y;
            a1.x += w1 * q0.x; a1.y += w1 * q0.y; a1.z += w1 * q1.x; a1.w += w1 * q1.y;
            a2.x += w2 * r0.x; a2.y += w2 * r0.y; a2.z += w2 * r1.x; a2.w += w2 * r1.y;
            a3.x += w3 * s0.x; a3.y += w3 * s0.y; a3.z += w3 * s1.x; a3.w += w3 * s1.y;
        }
        for (; s < len; s++) {
            float w0 = attn_s[s];
            uint2 v0 = xb[(size_t)s * (En / 4) + tid];
            float2 p0 = __half22float2(*reinterpret_cast<__half2*>(&v0.x));
            float2 p1 = __half22float2(*reinterpret_cast<__half2*>(&v0.y));
            a0.x += w0 * p0.x; a0.y += w0 * p0.y; a0.z += w0 * p1.x; a0.w += w0 * p1.y;
        }
        a0.x += a1.x + a2.x + a3.x;
        a0.y += a1.y + a2.y + a3.y;
        a0.z += a1.z + a2.z + a3.z;
        a0.w += a1.w + a2.w + a3.w;
        reinterpret_cast<float4*>(out)[(size_t)b * (En / 4) + tid] = a0;
    }

    // keep_attention (last batch only): zeros outside the bag
    if (b == Bn - 1 && tid < Sn) {
        int r = tid - start;
        out[(size_t)Bn * En + tid] = (r >= 0 && r < len) ? attn_s[r] : 0.0f;
    }
}

// ---------------------------------------------------------------------------
extern "C" void kernel_launch(void* const* d_in, const int* in_sizes, int n_in,
                              void* d_out, int out_size) {
    const float* x   = (const float*)d_in[0];
    const float* W   = (const float*)d_in[1];
    const float* u   = (const float*)d_in[2];
    const int*   doc = (const int*)d_in[3];
    float* out = (float*)d_out;

    conv_kernel<<<1024 + Bn * XBLK + 1, 256>>>((const float4*)W, (const float4*)x, doc);

    cudaFuncSetAttribute(gemm_kernel,
                         cudaFuncAttributeMaxDynamicSharedMemorySize, SMEM_TOTAL);
    gemm_kernel<<<GEMM_GRID, NTHR, SMEM_TOTAL>>>(u);

    finish_kernel<<<Bn, 256>>>(doc, out);
}